// round 1
// baseline (speedup 1.0000x reference)
#include <cuda_runtime.h>
#include <math.h>

#define B_   512
#define T_   60
#define E_   300
#define H_   512
#define M_   256
#define R_   1024          // 2*B rows (both sequences batched)
#define N4H  2048          // 4*H

// Scratch (static __device__ allocations — allowed)
__device__ float g_XZ[(size_t)T_ * R_ * N4H];  // x-projection + bias, [t][r][4H]
__device__ float g_Z [(size_t)R_ * N4H];       // per-step pre-activation
__device__ float g_H [(size_t)R_ * H_];
__device__ float g_C [(size_t)R_ * H_];

// ---------------------------------------------------------------------------
// init: zero h and c
// ---------------------------------------------------------------------------
__global__ void init_state_kernel() {
    int idx = blockIdx.x * blockDim.x + threadIdx.x;
    if (idx < R_ * H_) {
        g_H[idx] = 0.f;
        g_C[idx] = 0.f;
    }
}

// ---------------------------------------------------------------------------
// GEMM1: XZ[t][r][:] = emb[token(t,r)] @ Wx + bias
//   A: gathered embedding rows (K=300), B: lstm_kernel rows [0,300)
//   M = T_*R_ = 61440, N = 2048, K = 300
//   128x128 block tile, 8x8 per thread, BK=8
// ---------------------------------------------------------------------------
__global__ __launch_bounds__(256)
void gemm1_kernel(const int* __restrict__ in1, const int* __restrict__ in2,
                  const float* __restrict__ emb, const float* __restrict__ W,
                  const float* __restrict__ bias)
{
    __shared__ float As[8][128];
    __shared__ float Bs[8][128];
    __shared__ int   tok[128];

    const int tid = threadIdx.x;
    const int n0  = blockIdx.x * 128;
    const int m0  = blockIdx.y * 128;          // 128 | 1024 -> single t per block
    const int t   = m0 >> 10;
    const int rb  = m0 & 1023;

    if (tid < 128) {
        int r = rb + tid;
        int b = r & 511;
        tok[tid] = (r < 512) ? in1[b * T_ + t] : in2[b * T_ + t];
    }
    __syncthreads();

    float acc[8][8];
#pragma unroll
    for (int u = 0; u < 8; u++)
#pragma unroll
        for (int v = 0; v < 8; v++) acc[u][v] = 0.f;

    const int tx   = tid & 15;
    const int ty   = tid >> 4;
    const int arow = tid >> 1;        // 0..127
    const int ak0  = (tid & 1) * 4;   // 0 or 4
    const int bn   = tid & 127;
    const int bk0  = tid >> 7;        // 0 or 1

    for (int kk = 0; kk < E_; kk += 8) {
        const float* ap = emb + (size_t)tok[arow] * E_ + kk + ak0;
#pragma unroll
        for (int l = 0; l < 4; l++) {
            int k = ak0 + l;
            As[k][arow] = (kk + k < E_) ? ap[l] : 0.f;
        }
#pragma unroll
        for (int l = 0; l < 4; l++) {
            int k = bk0 + l * 2;
            Bs[k][bn] = (kk + k < E_) ? W[(size_t)(kk + k) * N4H + n0 + bn] : 0.f;
        }
        __syncthreads();
#pragma unroll
        for (int k = 0; k < 8; k++) {
            float4 a0 = *(const float4*)&As[k][ty * 8];
            float4 a1 = *(const float4*)&As[k][ty * 8 + 4];
            float4 b0 = *(const float4*)&Bs[k][tx * 8];
            float4 b1 = *(const float4*)&Bs[k][tx * 8 + 4];
            float a[8] = {a0.x, a0.y, a0.z, a0.w, a1.x, a1.y, a1.z, a1.w};
            float b[8] = {b0.x, b0.y, b0.z, b0.w, b1.x, b1.y, b1.z, b1.w};
#pragma unroll
            for (int u = 0; u < 8; u++)
#pragma unroll
                for (int v = 0; v < 8; v++) acc[u][v] = fmaf(a[u], b[v], acc[u][v]);
        }
        __syncthreads();
    }

#pragma unroll
    for (int u = 0; u < 8; u++) {
        size_t m    = (size_t)m0 + ty * 8 + u;
        size_t base = m * N4H + n0 + tx * 8;
#pragma unroll
        for (int v = 0; v < 8; v++)
            g_XZ[base + v] = acc[u][v] + bias[n0 + tx * 8 + v];
    }
}

// ---------------------------------------------------------------------------
// GEMM2 (per step): Z = H @ Wh + XZ[t]
//   M = 1024, N = 2048, K = 512. Wh = lstm_kernel rows [300, 812)
// ---------------------------------------------------------------------------
__global__ __launch_bounds__(256)
void gemm2_kernel(const float* __restrict__ W, int t)
{
    __shared__ float As[8][128];
    __shared__ float Bs[8][128];

    const int tid = threadIdx.x;
    const int n0  = blockIdx.x * 128;
    const int m0  = blockIdx.y * 128;

    float acc[8][8];
#pragma unroll
    for (int u = 0; u < 8; u++)
#pragma unroll
        for (int v = 0; v < 8; v++) acc[u][v] = 0.f;

    const int tx   = tid & 15;
    const int ty   = tid >> 4;
    const int arow = tid >> 1;
    const int ak0  = (tid & 1) * 4;
    const int bn   = tid & 127;
    const int bk0  = tid >> 7;

    const float* Wh = W + (size_t)E_ * N4H;

    for (int kk = 0; kk < H_; kk += 8) {
        const float* ap = g_H + (size_t)(m0 + arow) * H_ + kk + ak0;
#pragma unroll
        for (int l = 0; l < 4; l++)
            As[ak0 + l][arow] = ap[l];
#pragma unroll
        for (int l = 0; l < 4; l++) {
            int k = bk0 + l * 2;
            Bs[k][bn] = Wh[(size_t)(kk + k) * N4H + n0 + bn];
        }
        __syncthreads();
#pragma unroll
        for (int k = 0; k < 8; k++) {
            float4 a0 = *(const float4*)&As[k][ty * 8];
            float4 a1 = *(const float4*)&As[k][ty * 8 + 4];
            float4 b0 = *(const float4*)&Bs[k][tx * 8];
            float4 b1 = *(const float4*)&Bs[k][tx * 8 + 4];
            float a[8] = {a0.x, a0.y, a0.z, a0.w, a1.x, a1.y, a1.z, a1.w};
            float b[8] = {b0.x, b0.y, b0.z, b0.w, b1.x, b1.y, b1.z, b1.w};
#pragma unroll
            for (int u = 0; u < 8; u++)
#pragma unroll
                for (int v = 0; v < 8; v++) acc[u][v] = fmaf(a[u], b[v], acc[u][v]);
        }
        __syncthreads();
    }

    const size_t xzb = (size_t)t * R_ * N4H;
#pragma unroll
    for (int u = 0; u < 8; u++) {
        size_t m    = (size_t)m0 + ty * 8 + u;
        size_t base = m * N4H + n0 + tx * 8;
#pragma unroll
        for (int v = 0; v < 8; v++)
            g_Z[base + v] = acc[u][v] + g_XZ[xzb + base + v];
    }
}

// ---------------------------------------------------------------------------
// gates (per step): LSTM cell update with seq-length masking
// ---------------------------------------------------------------------------
__device__ __forceinline__ float sigmoidf_(float x) {
    return 1.f / (1.f + expf(-x));
}

__global__ void gates_kernel(const int* __restrict__ sl1,
                             const int* __restrict__ sl2, int t)
{
    int idx = blockIdx.x * blockDim.x + threadIdx.x;   // r*512 + hcol
    if (idx >= R_ * H_) return;
    int r    = idx >> 9;
    int hcol = idx & 511;
    int b    = r & 511;
    int sl   = (r < 512) ? sl1[b] : sl2[b];
    if (t >= sl) return;   // state frozen past sequence end

    size_t zb = (size_t)r * N4H + hcol;
    float zi = g_Z[zb];
    float zj = g_Z[zb + 512];
    float zf = g_Z[zb + 1024];
    float zo = g_Z[zb + 1536];

    float c  = g_C[idx];
    float nc = c * sigmoidf_(zf + 1.f) + sigmoidf_(zi) * tanhf(zj);
    g_C[idx] = nc;
    g_H[idx] = tanhf(nc) * sigmoidf_(zo);
}

// ---------------------------------------------------------------------------
// head: build h_combined [B, 2053], e1 = relu(hc@W1+b1), preds = e1@W2+b2
//   4 batch rows per block, 256 threads
// ---------------------------------------------------------------------------
__global__ __launch_bounds__(256)
void head_kernel(const int* __restrict__ sl1, const int* __restrict__ sl2,
                 const float* __restrict__ W1, const float* __restrict__ b1,
                 const float* __restrict__ W2, const float* __restrict__ b2,
                 float* __restrict__ out)
{
    __shared__ float hcs[4][2053];
    __shared__ float e1s[4][256];
    __shared__ float red[256];

    const int tid = threadIdx.x;
    const int b0  = blockIdx.x * 4;

    // build h_combined rows
    for (int rr = 0; rr < 4; rr++) {
        int bb = b0 + rr;
        const float* h1 = g_H + (size_t)bb * H_;
        const float* h2 = g_H + (size_t)(512 + bb) * H_;
        for (int k = tid; k < H_; k += 256) {
            float a = h1[k], c = h2[k];
            hcs[rr][k]         = a;
            hcs[rr][513 + k]   = c;
            hcs[rr][1026 + k]  = a - c;
            hcs[rr][1540 + k]  = a * c;
        }
        if (tid == 0) {
            float l1 = (float)sl1[bb] / (float)T_;
            float l2 = (float)sl2[bb] / (float)T_;
            hcs[rr][512]  = l1;
            hcs[rr][1025] = l2;
            hcs[rr][1538] = l1 - l2;
            hcs[rr][2052] = l1 * l2;
        }
    }
    __syncthreads();

    // h_dist = sum(h_sub^2) (513 terms) per row
    for (int rr = 0; rr < 4; rr++) {
        float v = 0.f;
        for (int k = tid; k < 513; k += 256) {
            float s = hcs[rr][1026 + k];
            v += s * s;
        }
        red[tid] = v;
        __syncthreads();
        for (int s = 128; s > 0; s >>= 1) {
            if (tid < s) red[tid] += red[tid + s];
            __syncthreads();
        }
        if (tid == 0) hcs[rr][1539] = red[0];
        __syncthreads();
    }

    // e1 = relu(hc @ W1 + b1): thread = output column, 4 rows at once
    float a0 = b1[tid], a1 = b1[tid], a2 = b1[tid], a3 = b1[tid];
    for (int k = 0; k < 2053; k++) {
        float w = W1[(size_t)k * M_ + tid];
        a0 = fmaf(hcs[0][k], w, a0);
        a1 = fmaf(hcs[1][k], w, a1);
        a2 = fmaf(hcs[2][k], w, a2);
        a3 = fmaf(hcs[3][k], w, a3);
    }
    e1s[0][tid] = fmaxf(a0, 0.f);
    e1s[1][tid] = fmaxf(a1, 0.f);
    e1s[2][tid] = fmaxf(a2, 0.f);
    e1s[3][tid] = fmaxf(a3, 0.f);
    __syncthreads();

    // preds = e1 @ W2 + b2 : 8 outputs (4 rows x 2 cols), one warp each
    int wid  = tid >> 5;
    int lane = tid & 31;
    int rr   = wid >> 1;
    int j    = wid & 1;
    float s = 0.f;
    for (int k = lane; k < M_; k += 32)
        s = fmaf(e1s[rr][k], W2[k * 2 + j], s);
#pragma unroll
    for (int off = 16; off > 0; off >>= 1)
        s += __shfl_down_sync(0xffffffffu, s, off);
    if (lane == 0)
        out[(size_t)(b0 + rr) * 2 + j] = s + b2[j];
}

// ---------------------------------------------------------------------------
// launch
// ---------------------------------------------------------------------------
extern "C" void kernel_launch(void* const* d_in, const int* in_sizes, int n_in,
                              void* d_out, int out_size)
{
    const int*   input1  = (const int*)  d_in[0];
    const int*   input2  = (const int*)  d_in[1];
    const int*   seqlen1 = (const int*)  d_in[2];
    const int*   seqlen2 = (const int*)  d_in[3];
    const float* emb     = (const float*)d_in[4];
    const float* kern    = (const float*)d_in[5];
    const float* bias    = (const float*)d_in[6];
    const float* W1      = (const float*)d_in[7];
    const float* b1      = (const float*)d_in[8];
    const float* W2      = (const float*)d_in[9];
    const float* b2      = (const float*)d_in[10];
    float*       out     = (float*)d_out;

    init_state_kernel<<<(R_ * H_ + 255) / 256, 256>>>();

    // x-projection for all timesteps, both sequences (includes bias)
    gemm1_kernel<<<dim3(N4H / 128, (T_ * R_) / 128), 256>>>(
        input1, input2, emb, kern, bias);

    // sequential recurrence
    for (int t = 0; t < T_; t++) {
        gemm2_kernel<<<dim3(N4H / 128, R_ / 128), 256>>>(kern, t);
        gates_kernel<<<(R_ * H_ + 255) / 256, 256>>>(seqlen1, seqlen2, t);
    }

    head_kernel<<<B_ / 4, 256>>>(seqlen1, seqlen2, W1, b1, W2, b2, out);
}

// round 3
// speedup vs baseline: 1.9240x; 1.9240x over previous
#include <cuda_runtime.h>
#include <cuda_bf16.h>
#include <math.h>
#include <stdint.h>

#define B_   512
#define T_   60
#define V_   50000
#define E_   300
#define EP_  320          // E padded to multiple of 64
#define H_   512
#define M_   256
#define R_   1024         // 2*B rows (both sequences batched)
#define N4H  2048         // 4*H (gate-interleaved permuted layout)
#define KH_  512

// Feature gate: tcgen05 only exists in the arch-specific (sm_103a/sm_100a)
// compilation passes. The plain compute_103/sm_103 pass gets an FFMA fallback.
#if defined(__CUDA_ARCH__) && (defined(__CUDA_ARCH_FEAT_SM103_ALL) || \
                               defined(__CUDA_ARCH_FEAT_SM100_ALL) || \
                               (defined(__CUDA_ARCH_SPECIFIC__) && (__CUDA_ARCH_SPECIFIC__ >= 1000)))
#define HAS_TC 1
#else
#define HAS_TC 0
#endif

// ---------------------------------------------------------------------------
// Device scratch (static allocations — allowed)
// ---------------------------------------------------------------------------
__device__ __align__(16) float g_XZ[(size_t)T_ * R_ * N4H];   // x-proj + bias, permuted cols
__device__ __align__(16) float g_H[R_ * H_];
__device__ __align__(16) float g_C[R_ * H_];
__device__ __align__(16) __nv_bfloat16 g_Hhi[2][R_ * H_];     // double-buffered H splits
__device__ __align__(16) __nv_bfloat16 g_Hlo[2][R_ * H_];
__device__ __align__(16) __nv_bfloat16 g_Ehi[(size_t)V_ * EP_];
__device__ __align__(16) __nv_bfloat16 g_Elo[(size_t)V_ * EP_];
__device__ __align__(16) __nv_bfloat16 g_WxThi[N4H * EP_];    // [n_perm][k], K-major
__device__ __align__(16) __nv_bfloat16 g_WxTlo[N4H * EP_];
__device__ __align__(16) __nv_bfloat16 g_WhThi[N4H * KH_];
__device__ __align__(16) __nv_bfloat16 g_WhTlo[N4H * KH_];

__device__ __forceinline__ float sigmoidf_(float x) { return 1.f / (1.f + expf(-x)); }

#if HAS_TC
// ---------------------------------------------------------------------------
// PTX helpers (sm_103a only)
// ---------------------------------------------------------------------------
__device__ __forceinline__ uint32_t smem_u32(const void* p) {
    uint32_t a;
    asm("{ .reg .u64 t; cvta.to.shared.u64 t, %1; cvt.u32.u64 %0, t; }" : "=r"(a) : "l"(p));
    return a;
}
__device__ __forceinline__ uint32_t elect_one() {
    uint32_t p;
    asm volatile("{ .reg .pred p; elect.sync _|p, 0xFFFFFFFF; selp.b32 %0, 1, 0, p; }" : "=r"(p));
    return p;
}

// idesc: c=F32, a=BF16 K-major, b=BF16 K-major, M=128, N=128
#define IDESC_128x128 0x8200490u
// SW128 desc base: layout=2, version=1, SBO=64, LBO=1
#define DESC_BASE ((2ull << 61) | (1ull << 46) | (64ull << 32) | (1ull << 16))

__device__ __forceinline__ uint64_t mk_desc(uint32_t smem_addr) {
    return DESC_BASE | ((uint64_t)(smem_addr >> 4) & 0x3FFF);
}

__device__ __forceinline__ void mma_f16_ss(uint32_t d, uint64_t ad, uint64_t bd, uint32_t acc) {
    asm volatile(
        "{\n\t.reg .pred p;\n\tsetp.ne.u32 p, %5, 0;\n\t"
        "tcgen05.mma.cta_group::1.kind::f16 [%0], %1, %2, %3, {%4, %4, %4, %4}, p;\n\t}\n"
        :: "r"(d), "l"(ad), "l"(bd), "r"(IDESC_128x128), "r"(0u), "r"(acc)
        : "memory");
}

__device__ __forceinline__ void mbar_wait(uint32_t mbar, uint32_t parity) {
    asm volatile(
        "{\n\t.reg .pred P;\n"
        "W_%=:\n\tmbarrier.try_wait.parity.acquire.cta.shared::cta.b64 P, [%0], %1, 0x989680;\n"
        "\t@P bra.uni D_%=;\n\tbra.uni W_%=;\n"
        "D_%=:\n\t}\n"
        :: "r"(mbar), "r"(parity) : "memory");
}

#define LDTM_X32(r, addr) \
    asm volatile( \
        "tcgen05.ld.sync.aligned.32x32b.x32.b32 " \
        "{%0, %1, %2, %3, %4, %5, %6, %7, " \
        " %8, %9, %10, %11, %12, %13, %14, %15, " \
        " %16, %17, %18, %19, %20, %21, %22, %23, " \
        " %24, %25, %26, %27, %28, %29, %30, %31}, [%32];" \
        : "=r"((r)[0]),  "=r"((r)[1]),  "=r"((r)[2]),  "=r"((r)[3]), \
          "=r"((r)[4]),  "=r"((r)[5]),  "=r"((r)[6]),  "=r"((r)[7]), \
          "=r"((r)[8]),  "=r"((r)[9]),  "=r"((r)[10]), "=r"((r)[11]), \
          "=r"((r)[12]), "=r"((r)[13]), "=r"((r)[14]), "=r"((r)[15]), \
          "=r"((r)[16]), "=r"((r)[17]), "=r"((r)[18]), "=r"((r)[19]), \
          "=r"((r)[20]), "=r"((r)[21]), "=r"((r)[22]), "=r"((r)[23]), \
          "=r"((r)[24]), "=r"((r)[25]), "=r"((r)[26]), "=r"((r)[27]), \
          "=r"((r)[28]), "=r"((r)[29]), "=r"((r)[30]), "=r"((r)[31]) \
        : "r"(addr))

// Issue one K=64 chunk: 4 k-steps x 3 split-products, then commit.
__device__ __forceinline__ void issue_chunk(uint32_t d, uint32_t sAh, uint32_t sAl,
                                            uint32_t sBh, uint32_t sBl, int first,
                                            uint32_t mbar) {
    uint64_t ah = mk_desc(sAh), al = mk_desc(sAl);
    uint64_t bh = mk_desc(sBh), bl = mk_desc(sBl);
#pragma unroll
    for (int ks = 0; ks < 4; ks++) {
        mma_f16_ss(d, ah + ks * 2, bh + ks * 2, (first && ks == 0) ? 0u : 1u);
        mma_f16_ss(d, ah + ks * 2, bl + ks * 2, 1u);
        mma_f16_ss(d, al + ks * 2, bh + ks * 2, 1u);
    }
    asm volatile(
        "tcgen05.commit.cta_group::1.mbarrier::arrive::one.shared::cluster.b64 [%0];"
        :: "r"(mbar) : "memory");
}

// thread = row; copy 128 bytes (64 bf16) from gmem into SW128-swizzled smem row
__device__ __forceinline__ void load_row128(char* dst_base, int row, const uint4* src) {
#pragma unroll
    for (int i = 0; i < 8; i++) {
        uint32_t bo = (uint32_t)row * 128 + i * 16;
        uint32_t sw = bo ^ ((bo >> 3) & 0x70);
        *(uint4*)(dst_base + sw) = src[i];
    }
}
#endif  // HAS_TC

// SMEM layout (dynamic, 66560 bytes)
#define SM_TILE_A_HI 1024
#define SM_TILE_A_LO (1024 + 16384)
#define SM_TILE_B_HI (1024 + 32768)
#define SM_TILE_B_LO (1024 + 49152)
#define SMEM_BYTES   (1024 + 65536)

// ---------------------------------------------------------------------------
// init + split kernels
// ---------------------------------------------------------------------------
__global__ void init_state_kernel() {
    int idx = blockIdx.x * blockDim.x + threadIdx.x;
    if (idx < R_ * H_) {
        g_H[idx] = 0.f;
        g_C[idx] = 0.f;
        g_Hhi[0][idx] = __float2bfloat16(0.f);
        g_Hlo[0][idx] = __float2bfloat16(0.f);
    }
}

__global__ void split_emb_kernel(const float* __restrict__ emb) {
    size_t idx = (size_t)blockIdx.x * blockDim.x + threadIdx.x;
    if (idx >= (size_t)V_ * EP_) return;
    int k = (int)(idx % EP_);
    size_t v = idx / EP_;
    float x = (k < E_) ? emb[v * E_ + k] : 0.f;
    __nv_bfloat16 hi = __float2bfloat16(x);
    g_Ehi[idx] = hi;
    g_Elo[idx] = __float2bfloat16(x - __bfloat162float(hi));
}

// Wx transposed + gate-permuted: out[n_perm][k], n_perm = hcol*4+g, src col = g*512+hcol
__global__ void split_wx_kernel(const float* __restrict__ kern) {
    int idx = blockIdx.x * blockDim.x + threadIdx.x;
    if (idx >= N4H * EP_) return;
    int n = idx / EP_, k = idx % EP_;
    int nsrc = (n & 3) * H_ + (n >> 2);
    float x = (k < E_) ? kern[(size_t)k * N4H + nsrc] : 0.f;
    __nv_bfloat16 hi = __float2bfloat16(x);
    g_WxThi[idx] = hi;
    g_WxTlo[idx] = __float2bfloat16(x - __bfloat162float(hi));
}

__global__ void split_wh_kernel(const float* __restrict__ kern) {
    int idx = blockIdx.x * blockDim.x + threadIdx.x;
    if (idx >= N4H * KH_) return;
    int n = idx / KH_, k = idx % KH_;
    int nsrc = (n & 3) * H_ + (n >> 2);
    float x = kern[(size_t)(E_ + k) * N4H + nsrc];
    __nv_bfloat16 hi = __float2bfloat16(x);
    g_WhThi[idx] = hi;
    g_WhTlo[idx] = __float2bfloat16(x - __bfloat162float(hi));
}

// ---------------------------------------------------------------------------
// x-projection GEMM: XZ[t][r][n_perm] = emb[token] @ Wx + bias
//   grid: (16 N-tiles, 480 M-tiles), 128 threads, M-tile=128 rows (single t)
// ---------------------------------------------------------------------------
__global__ __launch_bounds__(128)
void xproj_kernel(const int* __restrict__ in1, const int* __restrict__ in2,
                  const float* __restrict__ bias)
{
    const int tid = threadIdx.x;
    const int n0 = blockIdx.x * 128;
    const int m0 = blockIdx.y * 128;
    const int t  = m0 >> 10;

    const int rr = (m0 & 1023) + tid;
    const int bb = rr & 511;
    const int token = (rr < 512) ? in1[bb * T_ + t] : in2[bb * T_ + t];

#if HAS_TC
    extern __shared__ char smem[];
    const int wid = tid >> 5;
    const int lane = tid & 31;
    uint32_t smem_base = smem_u32(smem);
    uint32_t mbar = smem_base + 8;

    if (wid == 0) {
        asm volatile("tcgen05.alloc.cta_group::1.sync.aligned.shared::cta.b32 [%0], %1;"
                     :: "r"(smem_base), "r"(128u) : "memory");
        asm volatile("tcgen05.relinquish_alloc_permit.cta_group::1.sync.aligned;");
    }
    if (tid == 0)
        asm volatile("mbarrier.init.shared.b64 [%0], 1;" :: "r"(mbar) : "memory");
    __syncthreads();
    uint32_t tmem;
    asm volatile("ld.shared.b32 %0, [%1];" : "=r"(tmem) : "r"(smem_base));

    const __nv_bfloat16* Ah = g_Ehi + (size_t)token * EP_;
    const __nv_bfloat16* Al = g_Elo + (size_t)token * EP_;
    const __nv_bfloat16* Bh = g_WxThi + (size_t)(n0 + tid) * EP_;
    const __nv_bfloat16* Bl = g_WxTlo + (size_t)(n0 + tid) * EP_;

    for (int ch = 0; ch < 5; ch++) {
        int kk = ch * 64;
        load_row128(smem + SM_TILE_A_HI, tid, (const uint4*)(Ah + kk));
        load_row128(smem + SM_TILE_A_LO, tid, (const uint4*)(Al + kk));
        load_row128(smem + SM_TILE_B_HI, tid, (const uint4*)(Bh + kk));
        load_row128(smem + SM_TILE_B_LO, tid, (const uint4*)(Bl + kk));
        asm volatile("fence.proxy.async.shared::cta;" ::: "memory");
        __syncthreads();
        if (wid == 0 && elect_one())
            issue_chunk(tmem, smem_base + SM_TILE_A_HI, smem_base + SM_TILE_A_LO,
                        smem_base + SM_TILE_B_HI, smem_base + SM_TILE_B_LO,
                        ch == 0, mbar);
        mbar_wait(mbar, (uint32_t)(ch & 1));
    }
    asm volatile("tcgen05.fence::after_thread_sync;" ::: "memory");

    // epilogue: D + bias -> XZ (permuted layout)
    const int m = m0 + wid * 32 + lane;
    const int hc0 = blockIdx.x * 32;
    float* dst = g_XZ + (size_t)m * N4H + n0;

    for (int cg = 0; cg < 4; cg++) {
        uint32_t d[32];
        LDTM_X32(d, tmem + cg * 32);
        asm volatile("tcgen05.wait::ld.sync.aligned;" ::: "memory");
#pragma unroll
        for (int hh = 0; hh < 8; hh++) {
            int hcol = hc0 + cg * 8 + hh;
            float4 v;
            v.x = __uint_as_float(d[hh * 4 + 0]) + bias[0 * H_ + hcol];
            v.y = __uint_as_float(d[hh * 4 + 1]) + bias[1 * H_ + hcol];
            v.z = __uint_as_float(d[hh * 4 + 2]) + bias[2 * H_ + hcol];
            v.w = __uint_as_float(d[hh * 4 + 3]) + bias[3 * H_ + hcol];
            *(float4*)(dst + cg * 32 + hh * 4) = v;
        }
    }
    __syncthreads();
    if (tid == 0)
        asm volatile("mbarrier.inval.shared.b64 [%0];" :: "r"(mbar) : "memory");
    if (wid == 0)
        asm volatile("tcgen05.dealloc.cta_group::1.sync.aligned.b32 %0, %1;"
                     :: "r"(tmem), "r"(128u));
#else
    // FFMA fallback (compiled for non-'a' gencode passes; never runs on GB300)
    const __nv_bfloat16* Ah = g_Ehi + (size_t)token * EP_;
    const __nv_bfloat16* Al = g_Elo + (size_t)token * EP_;
    float* dst = g_XZ + (size_t)(m0 + tid) * N4H;
    for (int nch = 0; nch < 16; nch++) {
        float acc[8] = {0, 0, 0, 0, 0, 0, 0, 0};
        for (int k = 0; k < EP_; k++) {
            float a = __bfloat162float(Ah[k]) + __bfloat162float(Al[k]);
#pragma unroll
            for (int j = 0; j < 8; j++) {
                size_t bidx = (size_t)(n0 + nch * 8 + j) * EP_ + k;
                float b = __bfloat162float(g_WxThi[bidx]) + __bfloat162float(g_WxTlo[bidx]);
                acc[j] = fmaf(a, b, acc[j]);
            }
        }
#pragma unroll
        for (int j = 0; j < 8; j++) {
            int n = n0 + nch * 8 + j;
            dst[n] = acc[j] + bias[(n & 3) * H_ + (n >> 2)];
        }
    }
#endif
}

// ---------------------------------------------------------------------------
// fused LSTM step: Z = H@Wh + XZ[t]; gates; update C, H, H_hi/lo (ping-pong)
//   grid: (16 N-tiles, 8 M-tiles), 128 threads
// ---------------------------------------------------------------------------
__global__ __launch_bounds__(128)
void lstm_step_kernel(const int* __restrict__ sl1, const int* __restrict__ sl2, int t)
{
    const int tid = threadIdx.x;
    const int n0 = blockIdx.x * 128;
    const int m0 = blockIdx.y * 128;
    const int rb = t & 1, wb = (t + 1) & 1;

#if HAS_TC
    extern __shared__ char smem[];
    const int wid = tid >> 5;
    const int lane = tid & 31;
    uint32_t smem_base = smem_u32(smem);
    uint32_t mbar = smem_base + 8;

    if (wid == 0) {
        asm volatile("tcgen05.alloc.cta_group::1.sync.aligned.shared::cta.b32 [%0], %1;"
                     :: "r"(smem_base), "r"(128u) : "memory");
        asm volatile("tcgen05.relinquish_alloc_permit.cta_group::1.sync.aligned;");
    }
    if (tid == 0)
        asm volatile("mbarrier.init.shared.b64 [%0], 1;" :: "r"(mbar) : "memory");
    __syncthreads();
    uint32_t tmem;
    asm volatile("ld.shared.b32 %0, [%1];" : "=r"(tmem) : "r"(smem_base));

    const __nv_bfloat16* Ah = g_Hhi[rb] + (size_t)(m0 + tid) * KH_;
    const __nv_bfloat16* Al = g_Hlo[rb] + (size_t)(m0 + tid) * KH_;
    const __nv_bfloat16* Bh = g_WhThi + (size_t)(n0 + tid) * KH_;
    const __nv_bfloat16* Bl = g_WhTlo + (size_t)(n0 + tid) * KH_;

    for (int ch = 0; ch < 8; ch++) {
        int kk = ch * 64;
        load_row128(smem + SM_TILE_A_HI, tid, (const uint4*)(Ah + kk));
        load_row128(smem + SM_TILE_A_LO, tid, (const uint4*)(Al + kk));
        load_row128(smem + SM_TILE_B_HI, tid, (const uint4*)(Bh + kk));
        load_row128(smem + SM_TILE_B_LO, tid, (const uint4*)(Bl + kk));
        asm volatile("fence.proxy.async.shared::cta;" ::: "memory");
        __syncthreads();
        if (wid == 0 && elect_one())
            issue_chunk(tmem, smem_base + SM_TILE_A_HI, smem_base + SM_TILE_A_LO,
                        smem_base + SM_TILE_B_HI, smem_base + SM_TILE_B_LO,
                        ch == 0, mbar);
        mbar_wait(mbar, (uint32_t)(ch & 1));
    }
    asm volatile("tcgen05.fence::after_thread_sync;" ::: "memory");

    // fused gates epilogue
    const int r = m0 + wid * 32 + lane;
    const int b = r & 511;
    const int sl = (r < 512) ? sl1[b] : sl2[b];
    const bool valid = (t < sl);
    const int hc0 = blockIdx.x * 32;
    const float* xz = g_XZ + ((size_t)t * R_ + r) * N4H + n0;

    for (int cg = 0; cg < 4; cg++) {
        uint32_t d[32];
        LDTM_X32(d, tmem + cg * 32);
        asm volatile("tcgen05.wait::ld.sync.aligned;" ::: "memory");
#pragma unroll
        for (int hh = 0; hh < 8; hh++) {
            int hcol = hc0 + cg * 8 + hh;
            float4 x = *(const float4*)(xz + cg * 32 + hh * 4);
            float zi = __uint_as_float(d[hh * 4 + 0]) + x.x;
            float zj = __uint_as_float(d[hh * 4 + 1]) + x.y;
            float zf = __uint_as_float(d[hh * 4 + 2]) + x.z;
            float zo = __uint_as_float(d[hh * 4 + 3]) + x.w;
            int idx = r * H_ + hcol;
            float co = g_C[idx];
            float ho = g_H[idx];
            float nc = co * sigmoidf_(zf + 1.f) + sigmoidf_(zi) * tanhf(zj);
            float nh = tanhf(nc) * sigmoidf_(zo);
            if (!valid) { nc = co; nh = ho; }
            g_C[idx] = nc;
            g_H[idx] = nh;
            __nv_bfloat16 hi = __float2bfloat16(nh);
            g_Hhi[wb][idx] = hi;
            g_Hlo[wb][idx] = __float2bfloat16(nh - __bfloat162float(hi));
        }
    }
    __syncthreads();
    if (tid == 0)
        asm volatile("mbarrier.inval.shared.b64 [%0];" :: "r"(mbar) : "memory");
    if (wid == 0)
        asm volatile("tcgen05.dealloc.cta_group::1.sync.aligned.b32 %0, %1;"
                     :: "r"(tmem), "r"(128u));
#else
    // FFMA fallback (compiled for non-'a' gencode passes; never runs on GB300)
    const int r = m0 + tid;
    const int b = r & 511;
    const int sl = (r < 512) ? sl1[b] : sl2[b];
    const bool valid = (t < sl);
    const __nv_bfloat16* Ah = g_Hhi[rb] + (size_t)r * KH_;
    const __nv_bfloat16* Al = g_Hlo[rb] + (size_t)r * KH_;
    const float* xz = g_XZ + ((size_t)t * R_ + r) * N4H;

    for (int hi_i = 0; hi_i < 32; hi_i++) {
        int n = n0 + hi_i * 4;
        float acc[4] = {0, 0, 0, 0};
        for (int k = 0; k < KH_; k++) {
            float a = __bfloat162float(Ah[k]) + __bfloat162float(Al[k]);
#pragma unroll
            for (int g = 0; g < 4; g++) {
                size_t bidx = (size_t)(n + g) * KH_ + k;
                float bw = __bfloat162float(g_WhThi[bidx]) + __bfloat162float(g_WhTlo[bidx]);
                acc[g] = fmaf(a, bw, acc[g]);
            }
        }
        float zi = acc[0] + xz[n + 0];
        float zj = acc[1] + xz[n + 1];
        float zf = acc[2] + xz[n + 2];
        float zo = acc[3] + xz[n + 3];
        int hcol = n >> 2;
        int idx = r * H_ + hcol;
        float co = g_C[idx];
        float ho = g_H[idx];
        float nc = co * sigmoidf_(zf + 1.f) + sigmoidf_(zi) * tanhf(zj);
        float nh = tanhf(nc) * sigmoidf_(zo);
        if (!valid) { nc = co; nh = ho; }
        g_C[idx] = nc;
        g_H[idx] = nh;
        __nv_bfloat16 hb = __float2bfloat16(nh);
        g_Hhi[wb][idx] = hb;
        g_Hlo[wb][idx] = __float2bfloat16(nh - __bfloat162float(hb));
    }
#endif
}

// ---------------------------------------------------------------------------
// head (10us, not a bottleneck)
// ---------------------------------------------------------------------------
__global__ __launch_bounds__(256)
void head_kernel(const int* __restrict__ sl1, const int* __restrict__ sl2,
                 const float* __restrict__ W1, const float* __restrict__ b1,
                 const float* __restrict__ W2, const float* __restrict__ b2,
                 float* __restrict__ out)
{
    __shared__ float hcs[4][2053];
    __shared__ float e1s[4][256];
    __shared__ float red[256];

    const int tid = threadIdx.x;
    const int b0  = blockIdx.x * 4;

    for (int rr = 0; rr < 4; rr++) {
        int bb = b0 + rr;
        const float* h1 = g_H + (size_t)bb * H_;
        const float* h2 = g_H + (size_t)(512 + bb) * H_;
        for (int k = tid; k < H_; k += 256) {
            float a = h1[k], c = h2[k];
            hcs[rr][k]        = a;
            hcs[rr][513 + k]  = c;
            hcs[rr][1026 + k] = a - c;
            hcs[rr][1540 + k] = a * c;
        }
        if (tid == 0) {
            float l1 = (float)sl1[bb] / (float)T_;
            float l2 = (float)sl2[bb] / (float)T_;
            hcs[rr][512]  = l1;
            hcs[rr][1025] = l2;
            hcs[rr][1538] = l1 - l2;
            hcs[rr][2052] = l1 * l2;
        }
    }
    __syncthreads();

    for (int rr = 0; rr < 4; rr++) {
        float v = 0.f;
        for (int k = tid; k < 513; k += 256) {
            float s = hcs[rr][1026 + k];
            v += s * s;
        }
        red[tid] = v;
        __syncthreads();
        for (int s = 128; s > 0; s >>= 1) {
            if (tid < s) red[tid] += red[tid + s];
            __syncthreads();
        }
        if (tid == 0) hcs[rr][1539] = red[0];
        __syncthreads();
    }

    float a0 = b1[tid], a1 = b1[tid], a2 = b1[tid], a3 = b1[tid];
    for (int k = 0; k < 2053; k++) {
        float w = W1[(size_t)k * M_ + tid];
        a0 = fmaf(hcs[0][k], w, a0);
        a1 = fmaf(hcs[1][k], w, a1);
        a2 = fmaf(hcs[2][k], w, a2);
        a3 = fmaf(hcs[3][k], w, a3);
    }
    e1s[0][tid] = fmaxf(a0, 0.f);
    e1s[1][tid] = fmaxf(a1, 0.f);
    e1s[2][tid] = fmaxf(a2, 0.f);
    e1s[3][tid] = fmaxf(a3, 0.f);
    __syncthreads();

    int wid  = tid >> 5;
    int lane = tid & 31;
    int rr   = wid >> 1;
    int j    = wid & 1;
    float s = 0.f;
    for (int k = lane; k < M_; k += 32)
        s = fmaf(e1s[rr][k], W2[k * 2 + j], s);
#pragma unroll
    for (int off = 16; off > 0; off >>= 1)
        s += __shfl_down_sync(0xffffffffu, s, off);
    if (lane == 0)
        out[(size_t)(b0 + rr) * 2 + j] = s + b2[j];
}

// ---------------------------------------------------------------------------
// launch
// ---------------------------------------------------------------------------
extern "C" void kernel_launch(void* const* d_in, const int* in_sizes, int n_in,
                              void* d_out, int out_size)
{
    const int*   input1  = (const int*)  d_in[0];
    const int*   input2  = (const int*)  d_in[1];
    const int*   seqlen1 = (const int*)  d_in[2];
    const int*   seqlen2 = (const int*)  d_in[3];
    const float* emb     = (const float*)d_in[4];
    const float* kern    = (const float*)d_in[5];
    const float* bias    = (const float*)d_in[6];
    const float* W1      = (const float*)d_in[7];
    const float* b1      = (const float*)d_in[8];
    const float* W2      = (const float*)d_in[9];
    const float* b2      = (const float*)d_in[10];
    float*       out     = (float*)d_out;

    cudaFuncSetAttribute(xproj_kernel, cudaFuncAttributeMaxDynamicSharedMemorySize, SMEM_BYTES);
    cudaFuncSetAttribute(lstm_step_kernel, cudaFuncAttributeMaxDynamicSharedMemorySize, SMEM_BYTES);

    init_state_kernel<<<(R_ * H_ + 255) / 256, 256>>>();
    split_emb_kernel<<<(int)(((size_t)V_ * EP_ + 255) / 256), 256>>>(emb);
    split_wx_kernel<<<(N4H * EP_ + 255) / 256, 256>>>(kern);
    split_wh_kernel<<<(N4H * KH_ + 255) / 256, 256>>>(kern);

    // x-projection for all timesteps, both sequences (tensor cores)
    xproj_kernel<<<dim3(16, (T_ * R_) / 128), 128, SMEM_BYTES>>>(input1, input2, bias);

    // sequential recurrence, fully fused per step
    for (int t = 0; t < T_; t++)
        lstm_step_kernel<<<dim3(16, 8), 128, SMEM_BYTES>>>(seqlen1, seqlen2, t);

    head_kernel<<<B_ / 4, 256>>>(seqlen1, seqlen2, W1, b1, W2, b2, out);
}

// round 4
// speedup vs baseline: 2.5012x; 1.3000x over previous
#include <cuda_runtime.h>
#include <cuda_bf16.h>
#include <math.h>
#include <stdint.h>

#define B_   512
#define T_   60
#define V_   50000
#define E_   300
#define EP_  320          // E padded to multiple of 64
#define H_   512
#define M_   256
#define R_   1024         // 2*B rows (both sequences batched)
#define N4H  2048         // 4*H (gate-interleaved permuted layout)
#define KH_  512

// Feature gate: tcgen05 only exists in the arch-specific (sm_103a/sm_100a)
// compilation passes. The plain compute_103/sm_103 pass gets an FFMA fallback.
#if defined(__CUDA_ARCH__) && (defined(__CUDA_ARCH_FEAT_SM103_ALL) || \
                               defined(__CUDA_ARCH_FEAT_SM100_ALL) || \
                               (defined(__CUDA_ARCH_SPECIFIC__) && (__CUDA_ARCH_SPECIFIC__ >= 1000)))
#define HAS_TC 1
#else
#define HAS_TC 0
#endif

// ---------------------------------------------------------------------------
// Device scratch (static allocations — allowed)
// ---------------------------------------------------------------------------
__device__ __align__(16) float g_XZ[(size_t)T_ * R_ * N4H];   // x-proj + bias, permuted cols
__device__ __align__(16) float g_H[R_ * H_];
__device__ __align__(16) float g_C[R_ * H_];
__device__ __align__(16) __nv_bfloat16 g_Hhi[2][R_ * H_];     // double-buffered H splits
__device__ __align__(16) __nv_bfloat16 g_Hlo[2][R_ * H_];
__device__ __align__(16) __nv_bfloat16 g_Ehi[(size_t)V_ * EP_];
__device__ __align__(16) __nv_bfloat16 g_Elo[(size_t)V_ * EP_];
__device__ __align__(16) __nv_bfloat16 g_WxThi[N4H * EP_];    // [n_perm][k], K-major
__device__ __align__(16) __nv_bfloat16 g_WxTlo[N4H * EP_];
__device__ __align__(16) __nv_bfloat16 g_WhThi[N4H * KH_];
__device__ __align__(16) __nv_bfloat16 g_WhTlo[N4H * KH_];

__device__ __forceinline__ float sigmoidf_(float x) { return 1.f / (1.f + expf(-x)); }

// SMEM layout: double-buffered chunk (4 tiles x 16KB per buffer)
#define SM_BUF(b)   (1024 + (b) * 65536)
#define SMEM_BYTES  (1024 + 2 * 65536)

#if HAS_TC
// ---------------------------------------------------------------------------
// PTX helpers (sm_103a only)
// ---------------------------------------------------------------------------
__device__ __forceinline__ uint32_t smem_u32(const void* p) {
    uint32_t a;
    asm("{ .reg .u64 t; cvta.to.shared.u64 t, %1; cvt.u32.u64 %0, t; }" : "=r"(a) : "l"(p));
    return a;
}
__device__ __forceinline__ uint32_t elect_one() {
    uint32_t p;
    asm volatile("{ .reg .pred p; elect.sync _|p, 0xFFFFFFFF; selp.b32 %0, 1, 0, p; }" : "=r"(p));
    return p;
}

// idesc: c=F32, a=BF16 K-major, b=BF16 K-major, M=128, N=128
#define IDESC_128x128 0x8200490u
// SW128 desc base: layout=2, version=1, SBO=64, LBO=1
#define DESC_BASE ((2ull << 61) | (1ull << 46) | (64ull << 32) | (1ull << 16))

__device__ __forceinline__ uint64_t mk_desc(uint32_t smem_addr) {
    return DESC_BASE | ((uint64_t)(smem_addr >> 4) & 0x3FFF);
}

__device__ __forceinline__ void mma_f16_ss(uint32_t d, uint64_t ad, uint64_t bd, uint32_t acc) {
    asm volatile(
        "{\n\t.reg .pred p;\n\tsetp.ne.u32 p, %5, 0;\n\t"
        "tcgen05.mma.cta_group::1.kind::f16 [%0], %1, %2, %3, {%4, %4, %4, %4}, p;\n\t}\n"
        :: "r"(d), "l"(ad), "l"(bd), "r"(IDESC_128x128), "r"(0u), "r"(acc)
        : "memory");
}

__device__ __forceinline__ void mbar_wait(uint32_t mbar, uint32_t parity) {
    asm volatile(
        "{\n\t.reg .pred P;\n"
        "W_%=:\n\tmbarrier.try_wait.parity.acquire.cta.shared::cta.b64 P, [%0], %1, 0x989680;\n"
        "\t@P bra.uni D_%=;\n\tbra.uni W_%=;\n"
        "D_%=:\n\t}\n"
        :: "r"(mbar), "r"(parity) : "memory");
}

#define LDTM_X32(r, addr) \
    asm volatile( \
        "tcgen05.ld.sync.aligned.32x32b.x32.b32 " \
        "{%0, %1, %2, %3, %4, %5, %6, %7, " \
        " %8, %9, %10, %11, %12, %13, %14, %15, " \
        " %16, %17, %18, %19, %20, %21, %22, %23, " \
        " %24, %25, %26, %27, %28, %29, %30, %31}, [%32];" \
        : "=r"((r)[0]),  "=r"((r)[1]),  "=r"((r)[2]),  "=r"((r)[3]), \
          "=r"((r)[4]),  "=r"((r)[5]),  "=r"((r)[6]),  "=r"((r)[7]), \
          "=r"((r)[8]),  "=r"((r)[9]),  "=r"((r)[10]), "=r"((r)[11]), \
          "=r"((r)[12]), "=r"((r)[13]), "=r"((r)[14]), "=r"((r)[15]), \
          "=r"((r)[16]), "=r"((r)[17]), "=r"((r)[18]), "=r"((r)[19]), \
          "=r"((r)[20]), "=r"((r)[21]), "=r"((r)[22]), "=r"((r)[23]), \
          "=r"((r)[24]), "=r"((r)[25]), "=r"((r)[26]), "=r"((r)[27]), \
          "=r"((r)[28]), "=r"((r)[29]), "=r"((r)[30]), "=r"((r)[31]) \
        : "r"(addr))

// Issue one K=64 chunk: 4 k-steps x 3 split-products, then commit.
__device__ __forceinline__ void issue_chunk(uint32_t d, uint32_t sbuf, int first,
                                            uint32_t mbar) {
    uint64_t ah = mk_desc(sbuf);
    uint64_t al = mk_desc(sbuf + 16384);
    uint64_t bh = mk_desc(sbuf + 32768);
    uint64_t bl = mk_desc(sbuf + 49152);
#pragma unroll
    for (int ks = 0; ks < 4; ks++) {
        mma_f16_ss(d, ah + ks * 2, bh + ks * 2, (first && ks == 0) ? 0u : 1u);
        mma_f16_ss(d, ah + ks * 2, bl + ks * 2, 1u);
        mma_f16_ss(d, al + ks * 2, bh + ks * 2, 1u);
    }
    asm volatile(
        "tcgen05.commit.cta_group::1.mbarrier::arrive::one.shared::cluster.b64 [%0];"
        :: "r"(mbar) : "memory");
}

// async-copy one 128x128B tile row (thread tid owns row tid) with SW128 swizzle
__device__ __forceinline__ void load_tile_async(uint32_t sdst, int tid,
                                                const __nv_bfloat16* src) {
#pragma unroll
    for (int i = 0; i < 8; i++) {
        uint32_t bo = (uint32_t)tid * 128 + i * 16;
        uint32_t sw = bo ^ ((bo >> 3) & 0x70);
        asm volatile("cp.async.cg.shared.global [%0], [%1], 16;"
                     :: "r"(sdst + sw), "l"((const char*)src + i * 16) : "memory");
    }
}

// Double-buffered pipelined GEMM mainloop. A/B pointers are per-thread row
// bases; chunk ch covers K elements [ch*64, ch*64+64).
template <int NCH>
__device__ __forceinline__ void run_pipeline(uint32_t smem_base, uint32_t tmem,
                                             uint32_t mbar, int tid, int wid,
                                             const __nv_bfloat16* Ah,
                                             const __nv_bfloat16* Al,
                                             const __nv_bfloat16* Bh,
                                             const __nv_bfloat16* Bl) {
    // prologue: chunk 0 in flight
    {
        uint32_t s0 = smem_base + SM_BUF(0);
        load_tile_async(s0,         tid, Ah);
        load_tile_async(s0 + 16384, tid, Al);
        load_tile_async(s0 + 32768, tid, Bh);
        load_tile_async(s0 + 49152, tid, Bl);
        asm volatile("cp.async.commit_group;" ::: "memory");
    }
#pragma unroll
    for (int ch = 0; ch < NCH; ch++) {
        uint32_t sbuf = smem_base + SM_BUF(ch & 1);
        if (ch + 1 < NCH) {
            // before overwriting buf (ch+1)&1, MMAs of chunk ch-1 must be done
            if (ch >= 1) mbar_wait(mbar, (uint32_t)((ch - 1) & 1));
            uint32_t sn = smem_base + SM_BUF((ch + 1) & 1);
            int kk = (ch + 1) * 64;
            load_tile_async(sn,         tid, Ah + kk);
            load_tile_async(sn + 16384, tid, Al + kk);
            load_tile_async(sn + 32768, tid, Bh + kk);
            load_tile_async(sn + 49152, tid, Bl + kk);
            asm volatile("cp.async.commit_group;" ::: "memory");
            asm volatile("cp.async.wait_group 1;" ::: "memory");
        } else {
            asm volatile("cp.async.wait_group 0;" ::: "memory");
        }
        asm volatile("fence.proxy.async.shared::cta;" ::: "memory");
        __syncthreads();
        if (wid == 0 && elect_one())
            issue_chunk(tmem, sbuf, ch == 0, mbar);
    }
    // tail: strictly alternating parity waits for the last two commits
    mbar_wait(mbar, (uint32_t)((NCH - 2) & 1));
    mbar_wait(mbar, (uint32_t)((NCH - 1) & 1));
    asm volatile("tcgen05.fence::after_thread_sync;" ::: "memory");
}
#endif  // HAS_TC

// ---------------------------------------------------------------------------
// init + split kernels
// ---------------------------------------------------------------------------
__global__ void init_state_kernel() {
    int idx = blockIdx.x * blockDim.x + threadIdx.x;
    if (idx < R_ * H_) {
        g_H[idx] = 0.f;
        g_C[idx] = 0.f;
        g_Hhi[0][idx] = __float2bfloat16(0.f);
        g_Hlo[0][idx] = __float2bfloat16(0.f);
    }
}

__global__ void split_emb_kernel(const float* __restrict__ emb) {
    size_t idx = (size_t)blockIdx.x * blockDim.x + threadIdx.x;
    if (idx >= (size_t)V_ * EP_) return;
    int k = (int)(idx % EP_);
    size_t v = idx / EP_;
    float x = (k < E_) ? emb[v * E_ + k] : 0.f;
    __nv_bfloat16 hi = __float2bfloat16(x);
    g_Ehi[idx] = hi;
    g_Elo[idx] = __float2bfloat16(x - __bfloat162float(hi));
}

// Wx transposed + gate-permuted: out[n_perm][k], n_perm = hcol*4+g, src col = g*512+hcol
__global__ void split_wx_kernel(const float* __restrict__ kern) {
    int idx = blockIdx.x * blockDim.x + threadIdx.x;
    if (idx >= N4H * EP_) return;
    int n = idx / EP_, k = idx % EP_;
    int nsrc = (n & 3) * H_ + (n >> 2);
    float x = (k < E_) ? kern[(size_t)k * N4H + nsrc] : 0.f;
    __nv_bfloat16 hi = __float2bfloat16(x);
    g_WxThi[idx] = hi;
    g_WxTlo[idx] = __float2bfloat16(x - __bfloat162float(hi));
}

__global__ void split_wh_kernel(const float* __restrict__ kern) {
    int idx = blockIdx.x * blockDim.x + threadIdx.x;
    if (idx >= N4H * KH_) return;
    int n = idx / KH_, k = idx % KH_;
    int nsrc = (n & 3) * H_ + (n >> 2);
    float x = kern[(size_t)(E_ + k) * N4H + nsrc];
    __nv_bfloat16 hi = __float2bfloat16(x);
    g_WhThi[idx] = hi;
    g_WhTlo[idx] = __float2bfloat16(x - __bfloat162float(hi));
}

// ---------------------------------------------------------------------------
// x-projection GEMM: XZ[t][r][n_perm] = emb[token] @ Wx + bias
//   grid: (16 N-tiles, 480 M-tiles), 128 threads, M-tile=128 rows (single t)
// ---------------------------------------------------------------------------
__global__ __launch_bounds__(128)
void xproj_kernel(const int* __restrict__ in1, const int* __restrict__ in2,
                  const float* __restrict__ bias)
{
    const int tid = threadIdx.x;
    const int n0 = blockIdx.x * 128;
    const int m0 = blockIdx.y * 128;
    const int t  = m0 >> 10;

    const int rr = (m0 & 1023) + tid;
    const int bb = rr & 511;
    const int token = (rr < 512) ? in1[bb * T_ + t] : in2[bb * T_ + t];

#if HAS_TC
    extern __shared__ char smem[];
    const int wid = tid >> 5;
    const int lane = tid & 31;
    uint32_t smem_base = smem_u32(smem);
    uint32_t mbar = smem_base + 8;

    if (wid == 0) {
        asm volatile("tcgen05.alloc.cta_group::1.sync.aligned.shared::cta.b32 [%0], %1;"
                     :: "r"(smem_base), "r"(128u) : "memory");
        asm volatile("tcgen05.relinquish_alloc_permit.cta_group::1.sync.aligned;");
    }
    if (tid == 0)
        asm volatile("mbarrier.init.shared.b64 [%0], 1;" :: "r"(mbar) : "memory");
    __syncthreads();
    uint32_t tmem;
    asm volatile("ld.shared.b32 %0, [%1];" : "=r"(tmem) : "r"(smem_base));

    run_pipeline<5>(smem_base, tmem, mbar, tid, wid,
                    g_Ehi + (size_t)token * EP_,
                    g_Elo + (size_t)token * EP_,
                    g_WxThi + (size_t)(n0 + tid) * EP_,
                    g_WxTlo + (size_t)(n0 + tid) * EP_);

    // epilogue: D + bias -> XZ (permuted layout)
    const int m = m0 + wid * 32 + lane;
    const int hc0 = blockIdx.x * 32;
    float* dst = g_XZ + (size_t)m * N4H + n0;

#pragma unroll
    for (int cg = 0; cg < 4; cg++) {
        uint32_t d[32];
        LDTM_X32(d, tmem + cg * 32);
        asm volatile("tcgen05.wait::ld.sync.aligned;" ::: "memory");
#pragma unroll
        for (int hh = 0; hh < 8; hh++) {
            int hcol = hc0 + cg * 8 + hh;
            float4 v;
            v.x = __uint_as_float(d[hh * 4 + 0]) + bias[0 * H_ + hcol];
            v.y = __uint_as_float(d[hh * 4 + 1]) + bias[1 * H_ + hcol];
            v.z = __uint_as_float(d[hh * 4 + 2]) + bias[2 * H_ + hcol];
            v.w = __uint_as_float(d[hh * 4 + 3]) + bias[3 * H_ + hcol];
            *(float4*)(dst + cg * 32 + hh * 4) = v;
        }
    }
    __syncthreads();
    if (tid == 0)
        asm volatile("mbarrier.inval.shared.b64 [%0];" :: "r"(mbar) : "memory");
    if (wid == 0)
        asm volatile("tcgen05.dealloc.cta_group::1.sync.aligned.b32 %0, %1;"
                     :: "r"(tmem), "r"(128u));
#else
    // FFMA fallback (compiled for non-'a' gencode passes; never runs on GB300)
    const __nv_bfloat16* Ah = g_Ehi + (size_t)token * EP_;
    const __nv_bfloat16* Al = g_Elo + (size_t)token * EP_;
    float* dst = g_XZ + (size_t)(m0 + tid) * N4H;
    for (int nch = 0; nch < 16; nch++) {
        float acc[8] = {0, 0, 0, 0, 0, 0, 0, 0};
        for (int k = 0; k < EP_; k++) {
            float a = __bfloat162float(Ah[k]) + __bfloat162float(Al[k]);
#pragma unroll
            for (int j = 0; j < 8; j++) {
                size_t bidx = (size_t)(n0 + nch * 8 + j) * EP_ + k;
                float b = __bfloat162float(g_WxThi[bidx]) + __bfloat162float(g_WxTlo[bidx]);
                acc[j] = fmaf(a, b, acc[j]);
            }
        }
#pragma unroll
        for (int j = 0; j < 8; j++) {
            int n = n0 + nch * 8 + j;
            dst[n] = acc[j] + bias[(n & 3) * H_ + (n >> 2)];
        }
    }
#endif
}

// ---------------------------------------------------------------------------
// fused LSTM step: Z = H@Wh + XZ[t]; gates; update C, H, H_hi/lo (ping-pong)
//   grid: (16 N-tiles, 8 M-tiles), 128 threads
// ---------------------------------------------------------------------------
__global__ __launch_bounds__(128)
void lstm_step_kernel(const int* __restrict__ sl1, const int* __restrict__ sl2, int t)
{
    const int tid = threadIdx.x;
    const int n0 = blockIdx.x * 128;
    const int m0 = blockIdx.y * 128;
    const int rb = t & 1, wb = (t + 1) & 1;

#if HAS_TC
    extern __shared__ char smem[];
    const int wid = tid >> 5;
    const int lane = tid & 31;
    uint32_t smem_base = smem_u32(smem);
    uint32_t mbar = smem_base + 8;

    if (wid == 0) {
        asm volatile("tcgen05.alloc.cta_group::1.sync.aligned.shared::cta.b32 [%0], %1;"
                     :: "r"(smem_base), "r"(128u) : "memory");
        asm volatile("tcgen05.relinquish_alloc_permit.cta_group::1.sync.aligned;");
    }
    if (tid == 0)
        asm volatile("mbarrier.init.shared.b64 [%0], 1;" :: "r"(mbar) : "memory");
    __syncthreads();
    uint32_t tmem;
    asm volatile("ld.shared.b32 %0, [%1];" : "=r"(tmem) : "r"(smem_base));

    run_pipeline<8>(smem_base, tmem, mbar, tid, wid,
                    g_Hhi[rb] + (size_t)(m0 + tid) * KH_,
                    g_Hlo[rb] + (size_t)(m0 + tid) * KH_,
                    g_WhThi + (size_t)(n0 + tid) * KH_,
                    g_WhTlo + (size_t)(n0 + tid) * KH_);

    // fused gates epilogue — vectorized state I/O
    const int r = m0 + wid * 32 + lane;
    const int b = r & 511;
    const int sl = (r < 512) ? sl1[b] : sl2[b];
    const bool valid = (t < sl);
    const int hc0 = blockIdx.x * 32;
    const int idx0 = r * H_ + hc0;
    const float* xz = g_XZ + ((size_t)t * R_ + r) * N4H + n0;

    float c[32], h[32];
#pragma unroll
    for (int i = 0; i < 8; i++) {
        *(float4*)&c[i * 4] = *(const float4*)(g_C + idx0 + i * 4);
        *(float4*)&h[i * 4] = *(const float4*)(g_H + idx0 + i * 4);
    }

#pragma unroll
    for (int cg = 0; cg < 4; cg++) {
        float4 xv[8];
#pragma unroll
        for (int hh = 0; hh < 8; hh++)
            xv[hh] = *(const float4*)(xz + cg * 32 + hh * 4);
        uint32_t d[32];
        LDTM_X32(d, tmem + cg * 32);
        asm volatile("tcgen05.wait::ld.sync.aligned;" ::: "memory");
#pragma unroll
        for (int hh = 0; hh < 8; hh++) {
            int j = cg * 8 + hh;
            float zi = __uint_as_float(d[hh * 4 + 0]) + xv[hh].x;
            float zj = __uint_as_float(d[hh * 4 + 1]) + xv[hh].y;
            float zf = __uint_as_float(d[hh * 4 + 2]) + xv[hh].z;
            float zo = __uint_as_float(d[hh * 4 + 3]) + xv[hh].w;
            float nc = c[j] * sigmoidf_(zf + 1.f) + sigmoidf_(zi) * tanhf(zj);
            float nh = tanhf(nc) * sigmoidf_(zo);
            if (valid) { c[j] = nc; h[j] = nh; }
        }
    }

    // vectorized write-back: C/H as float4, H splits as packed bf16x2
    uint32_t hi2[16], lo2[16];
#pragma unroll
    for (int j = 0; j < 16; j++) {
        float h0 = h[j * 2], h1 = h[j * 2 + 1];
        __nv_bfloat16 b0 = __float2bfloat16(h0);
        __nv_bfloat16 b1 = __float2bfloat16(h1);
        __nv_bfloat16 l0 = __float2bfloat16(h0 - __bfloat162float(b0));
        __nv_bfloat16 l1 = __float2bfloat16(h1 - __bfloat162float(b1));
        hi2[j] = (uint32_t)__bfloat16_as_ushort(b0) |
                 ((uint32_t)__bfloat16_as_ushort(b1) << 16);
        lo2[j] = (uint32_t)__bfloat16_as_ushort(l0) |
                 ((uint32_t)__bfloat16_as_ushort(l1) << 16);
    }
#pragma unroll
    for (int i = 0; i < 8; i++) {
        *(float4*)(g_C + idx0 + i * 4) = *(const float4*)&c[i * 4];
        *(float4*)(g_H + idx0 + i * 4) = *(const float4*)&h[i * 4];
    }
#pragma unroll
    for (int i = 0; i < 4; i++) {
        *(uint4*)(g_Hhi[wb] + idx0 + i * 8) = *(const uint4*)&hi2[i * 4];
        *(uint4*)(g_Hlo[wb] + idx0 + i * 8) = *(const uint4*)&lo2[i * 4];
    }

    __syncthreads();
    if (tid == 0)
        asm volatile("mbarrier.inval.shared.b64 [%0];" :: "r"(mbar) : "memory");
    if (wid == 0)
        asm volatile("tcgen05.dealloc.cta_group::1.sync.aligned.b32 %0, %1;"
                     :: "r"(tmem), "r"(128u));
#else
    // FFMA fallback (compiled for non-'a' gencode passes; never runs on GB300)
    const int r = m0 + tid;
    const int b = r & 511;
    const int sl = (r < 512) ? sl1[b] : sl2[b];
    const bool valid = (t < sl);
    const __nv_bfloat16* Ah = g_Hhi[rb] + (size_t)r * KH_;
    const __nv_bfloat16* Al = g_Hlo[rb] + (size_t)r * KH_;
    const float* xz = g_XZ + ((size_t)t * R_ + r) * N4H;

    for (int hi_i = 0; hi_i < 32; hi_i++) {
        int n = n0 + hi_i * 4;
        float acc[4] = {0, 0, 0, 0};
        for (int k = 0; k < KH_; k++) {
            float a = __bfloat162float(Ah[k]) + __bfloat162float(Al[k]);
#pragma unroll
            for (int g = 0; g < 4; g++) {
                size_t bidx = (size_t)(n + g) * KH_ + k;
                float bw = __bfloat162float(g_WhThi[bidx]) + __bfloat162float(g_WhTlo[bidx]);
                acc[g] = fmaf(a, bw, acc[g]);
            }
        }
        float zi = acc[0] + xz[n + 0];
        float zj = acc[1] + xz[n + 1];
        float zf = acc[2] + xz[n + 2];
        float zo = acc[3] + xz[n + 3];
        int hcol = n >> 2;
        int idx = r * H_ + hcol;
        float co = g_C[idx];
        float ho = g_H[idx];
        float nc = co * sigmoidf_(zf + 1.f) + sigmoidf_(zi) * tanhf(zj);
        float nh = tanhf(nc) * sigmoidf_(zo);
        if (!valid) { nc = co; nh = ho; }
        g_C[idx] = nc;
        g_H[idx] = nh;
        __nv_bfloat16 hb = __float2bfloat16(nh);
        g_Hhi[wb][idx] = hb;
        g_Hlo[wb][idx] = __float2bfloat16(nh - __bfloat162float(hb));
    }
#endif
}

// ---------------------------------------------------------------------------
// head (not a bottleneck)
// ---------------------------------------------------------------------------
__global__ __launch_bounds__(256)
void head_kernel(const int* __restrict__ sl1, const int* __restrict__ sl2,
                 const float* __restrict__ W1, const float* __restrict__ b1,
                 const float* __restrict__ W2, const float* __restrict__ b2,
                 float* __restrict__ out)
{
    __shared__ float hcs[4][2053];
    __shared__ float e1s[4][256];
    __shared__ float red[256];

    const int tid = threadIdx.x;
    const int b0  = blockIdx.x * 4;

    for (int rr = 0; rr < 4; rr++) {
        int bb = b0 + rr;
        const float* h1 = g_H + (size_t)bb * H_;
        const float* h2 = g_H + (size_t)(512 + bb) * H_;
        for (int k = tid; k < H_; k += 256) {
            float a = h1[k], c = h2[k];
            hcs[rr][k]        = a;
            hcs[rr][513 + k]  = c;
            hcs[rr][1026 + k] = a - c;
            hcs[rr][1540 + k] = a * c;
        }
        if (tid == 0) {
            float l1 = (float)sl1[bb] / (float)T_;
            float l2 = (float)sl2[bb] / (float)T_;
            hcs[rr][512]  = l1;
            hcs[rr][1025] = l2;
            hcs[rr][1538] = l1 - l2;
            hcs[rr][2052] = l1 * l2;
        }
    }
    __syncthreads();

    for (int rr = 0; rr < 4; rr++) {
        float v = 0.f;
        for (int k = tid; k < 513; k += 256) {
            float s = hcs[rr][1026 + k];
            v += s * s;
        }
        red[tid] = v;
        __syncthreads();
        for (int s = 128; s > 0; s >>= 1) {
            if (tid < s) red[tid] += red[tid + s];
            __syncthreads();
        }
        if (tid == 0) hcs[rr][1539] = red[0];
        __syncthreads();
    }

    float a0 = b1[tid], a1 = b1[tid], a2 = b1[tid], a3 = b1[tid];
    for (int k = 0; k < 2053; k++) {
        float w = W1[(size_t)k * M_ + tid];
        a0 = fmaf(hcs[0][k], w, a0);
        a1 = fmaf(hcs[1][k], w, a1);
        a2 = fmaf(hcs[2][k], w, a2);
        a3 = fmaf(hcs[3][k], w, a3);
    }
    e1s[0][tid] = fmaxf(a0, 0.f);
    e1s[1][tid] = fmaxf(a1, 0.f);
    e1s[2][tid] = fmaxf(a2, 0.f);
    e1s[3][tid] = fmaxf(a3, 0.f);
    __syncthreads();

    int wid  = tid >> 5;
    int lane = tid & 31;
    int rr   = wid >> 1;
    int j    = wid & 1;
    float s = 0.f;
    for (int k = lane; k < M_; k += 32)
        s = fmaf(e1s[rr][k], W2[k * 2 + j], s);
#pragma unroll
    for (int off = 16; off > 0; off >>= 1)
        s += __shfl_down_sync(0xffffffffu, s, off);
    if (lane == 0)
        out[(size_t)(b0 + rr) * 2 + j] = s + b2[j];
}

// ---------------------------------------------------------------------------
// launch
// ---------------------------------------------------------------------------
extern "C" void kernel_launch(void* const* d_in, const int* in_sizes, int n_in,
                              void* d_out, int out_size)
{
    const int*   input1  = (const int*)  d_in[0];
    const int*   input2  = (const int*)  d_in[1];
    const int*   seqlen1 = (const int*)  d_in[2];
    const int*   seqlen2 = (const int*)  d_in[3];
    const float* emb     = (const float*)d_in[4];
    const float* kern    = (const float*)d_in[5];
    const float* bias    = (const float*)d_in[6];
    const float* W1      = (const float*)d_in[7];
    const float* b1      = (const float*)d_in[8];
    const float* W2      = (const float*)d_in[9];
    const float* b2      = (const float*)d_in[10];
    float*       out     = (float*)d_out;

    cudaFuncSetAttribute(xproj_kernel, cudaFuncAttributeMaxDynamicSharedMemorySize, SMEM_BYTES);
    cudaFuncSetAttribute(lstm_step_kernel, cudaFuncAttributeMaxDynamicSharedMemorySize, SMEM_BYTES);

    init_state_kernel<<<(R_ * H_ + 255) / 256, 256>>>();
    split_emb_kernel<<<(int)(((size_t)V_ * EP_ + 255) / 256), 256>>>(emb);
    split_wx_kernel<<<(N4H * EP_ + 255) / 256, 256>>>(kern);
    split_wh_kernel<<<(N4H * KH_ + 255) / 256, 256>>>(kern);

    // x-projection for all timesteps, both sequences (tensor cores, pipelined)
    xproj_kernel<<<dim3(16, (T_ * R_) / 128), 128, SMEM_BYTES>>>(input1, input2, bias);

    // sequential recurrence, fully fused per step
    for (int t = 0; t < T_; t++)
        lstm_step_kernel<<<dim3(16, 8), 128, SMEM_BYTES>>>(seqlen1, seqlen2, t);

    head_kernel<<<B_ / 4, 256>>>(seqlen1, seqlen2, W1, b1, W2, b2, out);
}